// round 2
// baseline (speedup 1.0000x reference)
#include <cuda_runtime.h>
#include <cstdint>

// Problem dims (fixed by the dataset): B=4, L=4096, D=1024
#define DMODEL 1024
#define M_MAX  (4 * 4096)

// Intermediate h = g * sigmoid(o), 16384 x 1024 fp32 (64 MB static scratch)
__device__ float g_h[(size_t)M_MAX * DMODEL];

// ---------------------------------------------------------------------------
// helpers
// ---------------------------------------------------------------------------
__device__ __forceinline__ uint32_t smem_u32(const void* p) {
    return (uint32_t)__cvta_generic_to_shared(p);
}
__device__ __forceinline__ void cp16(uint32_t dst, const void* src) {
    asm volatile("cp.async.cg.shared.global [%0], [%1], 16;\n" ::"r"(dst), "l"(src));
}
__device__ __forceinline__ void cp_commit() {
    asm volatile("cp.async.commit_group;\n");
}
template <int N>
__device__ __forceinline__ void cp_wait() {
    asm volatile("cp.async.wait_group %0;\n" ::"n"(N));
}
__device__ __forceinline__ uint32_t f2tf(float x) {
    uint32_t r;
    asm("cvt.rna.tf32.f32 %0, %1;" : "=r"(r) : "f"(x));
    return r;
}
__device__ __forceinline__ void mma8(float* c, const uint32_t* a, const uint32_t* b) {
    asm volatile(
        "mma.sync.aligned.m16n8k8.row.col.f32.tf32.tf32.f32 "
        "{%0,%1,%2,%3}, {%4,%5,%6,%7}, {%8,%9}, {%0,%1,%2,%3};\n"
        : "+f"(c[0]), "+f"(c[1]), "+f"(c[2]), "+f"(c[3])
        : "r"(a[0]), "r"(a[1]), "r"(a[2]), "r"(a[3]), "r"(b[0]), "r"(b[1]));
}

// ---------------------------------------------------------------------------
// Kernel 1: fused  g = x@Wg, o = x@Wo, h = g*sigmoid(o)
// BM=128, BN=64, BK=16, 256 threads, warp grid 4(M) x 2(N), warp tile 32x32.
// Dual accumulators share the A tile/fragments -> 2 GEMMs for the LDS cost
// of ~1.5.
// ---------------------------------------------------------------------------
__global__ __launch_bounds__(256) void hgrn2_gate_gemm(
    const float* __restrict__ x, const float* __restrict__ Wp,
    const float* __restrict__ bp)
{
    __shared__ float As[2][128][20];  // pad 4: bank = (20r + k) % 32, conflict-free
    __shared__ float Bg[2][16][72];   // pad 8: bank = (8k + n) % 32, conflict-free
    __shared__ float Bo[2][16][72];

    const int t = threadIdx.x;
    const int lane = t & 31, wid = t >> 5;
    const int wm = wid & 3, wn = wid >> 2;
    const int m0 = blockIdx.y * 128;
    const int n0 = blockIdx.x * 64;

    float accG[2][4][4] = {};
    float accO[2][4][4] = {};

    // A-load indices (2 float4 per thread)
    const int ar0 = t >> 2;
    const int ac4 = (t & 3) << 2;
    // B-load indices (1 float4 per B-array per thread)
    const int br = t >> 4;
    const int bc4 = (t & 15) << 2;

    const size_t xrow0 = (size_t)(m0 + ar0) * DMODEL;
    const size_t xrow1 = (size_t)(m0 + ar0 + 64) * DMODEL;

#define LOAD_STAGE1(s, k0)                                                        \
    do {                                                                          \
        cp16(smem_u32(&As[s][ar0][ac4]),      x + xrow0 + (k0) + ac4);            \
        cp16(smem_u32(&As[s][ar0 + 64][ac4]), x + xrow1 + (k0) + ac4);            \
        cp16(smem_u32(&Bg[s][br][bc4]), Wp + (size_t)((k0) + br) * 3072 + n0 + bc4);          \
        cp16(smem_u32(&Bo[s][br][bc4]), Wp + (size_t)((k0) + br) * 3072 + 2048 + n0 + bc4);   \
        cp_commit();                                                              \
    } while (0)

    LOAD_STAGE1(0, 0);
    const int KIT = DMODEL / 16;

    for (int it = 0; it < KIT; ++it) {
        const int s = it & 1;
        if (it + 1 < KIT) {
            LOAD_STAGE1((it + 1) & 1, (it + 1) * 16);
            cp_wait<1>();
        } else {
            cp_wait<0>();
        }
        __syncthreads();

#pragma unroll
        for (int ks = 0; ks < 2; ++ks) {
            const int kb = ks * 8;
            uint32_t a[2][4], bg[4][2], bo[4][2];
#pragma unroll
            for (int mf = 0; mf < 2; ++mf) {
                const int r0 = wm * 32 + mf * 16 + (lane >> 2);
                const int kc = kb + (lane & 3);
                a[mf][0] = f2tf(As[s][r0][kc]);
                a[mf][1] = f2tf(As[s][r0 + 8][kc]);
                a[mf][2] = f2tf(As[s][r0][kc + 4]);
                a[mf][3] = f2tf(As[s][r0 + 8][kc + 4]);
            }
#pragma unroll
            for (int nf = 0; nf < 4; ++nf) {
                const int c0 = wn * 32 + nf * 8 + (lane >> 2);
                const int kr = kb + (lane & 3);
                bg[nf][0] = f2tf(Bg[s][kr][c0]);
                bg[nf][1] = f2tf(Bg[s][kr + 4][c0]);
                bo[nf][0] = f2tf(Bo[s][kr][c0]);
                bo[nf][1] = f2tf(Bo[s][kr + 4][c0]);
            }
#pragma unroll
            for (int mf = 0; mf < 2; ++mf)
#pragma unroll
                for (int nf = 0; nf < 4; ++nf) {
                    mma8(accG[mf][nf], a[mf], bg[nf]);
                    mma8(accO[mf][nf], a[mf], bo[nf]);
                }
        }
        __syncthreads();
    }

    // Epilogue: h = (g + bg) * sigmoid(o + bo)
#pragma unroll
    for (int mf = 0; mf < 2; ++mf) {
#pragma unroll
        for (int nf = 0; nf < 4; ++nf) {
            const int row = m0 + wm * 32 + mf * 16 + (lane >> 2);
            const int col = n0 + wn * 32 + nf * 8 + ((lane & 3) << 1);
            const float bg0 = bp[col],        bg1 = bp[col + 1];
            const float bo0 = bp[2048 + col], bo1 = bp[2048 + col + 1];
#pragma unroll
            for (int rr = 0; rr < 2; ++rr) {
                const float g0 = accG[mf][nf][rr * 2 + 0] + bg0;
                const float g1 = accG[mf][nf][rr * 2 + 1] + bg1;
                const float o0 = accO[mf][nf][rr * 2 + 0] + bo0;
                const float o1 = accO[mf][nf][rr * 2 + 1] + bo1;
                const float h0 = g0 * (1.0f / (1.0f + __expf(-o0)));
                const float h1 = g1 * (1.0f / (1.0f + __expf(-o1)));
                float2* p = reinterpret_cast<float2*>(
                    &g_h[(size_t)(row + rr * 8) * DMODEL + col]);
                *p = make_float2(h0, h1);
            }
        }
    }
#undef LOAD_STAGE1
}

// ---------------------------------------------------------------------------
// Kernel 2: out = h @ W_out + b_out
// Same structure, single accumulator. BM=128, BN=64, BK=16.
// ---------------------------------------------------------------------------
__global__ __launch_bounds__(256) void hgrn2_out_gemm(
    const float* __restrict__ Wout, const float* __restrict__ bout,
    float* __restrict__ out)
{
    __shared__ float As[2][128][20];
    __shared__ float Bs[2][16][72];

    const int t = threadIdx.x;
    const int lane = t & 31, wid = t >> 5;
    const int wm = wid & 3, wn = wid >> 2;
    const int m0 = blockIdx.y * 128;
    const int n0 = blockIdx.x * 64;

    float acc[2][4][4] = {};

    const int ar0 = t >> 2;
    const int ac4 = (t & 3) << 2;
    const int br = t >> 4;
    const int bc4 = (t & 15) << 2;

    const size_t hrow0 = (size_t)(m0 + ar0) * DMODEL;
    const size_t hrow1 = (size_t)(m0 + ar0 + 64) * DMODEL;

#define LOAD_STAGE2(s, k0)                                                        \
    do {                                                                          \
        cp16(smem_u32(&As[s][ar0][ac4]),      g_h + hrow0 + (k0) + ac4);          \
        cp16(smem_u32(&As[s][ar0 + 64][ac4]), g_h + hrow1 + (k0) + ac4);          \
        cp16(smem_u32(&Bs[s][br][bc4]), Wout + (size_t)((k0) + br) * DMODEL + n0 + bc4); \
        cp_commit();                                                              \
    } while (0)

    LOAD_STAGE2(0, 0);
    const int KIT = DMODEL / 16;

    for (int it = 0; it < KIT; ++it) {
        const int s = it & 1;
        if (it + 1 < KIT) {
            LOAD_STAGE2((it + 1) & 1, (it + 1) * 16);
            cp_wait<1>();
        } else {
            cp_wait<0>();
        }
        __syncthreads();

#pragma unroll
        for (int ks = 0; ks < 2; ++ks) {
            const int kb = ks * 8;
            uint32_t a[2][4], b[4][2];
#pragma unroll
            for (int mf = 0; mf < 2; ++mf) {
                const int r0 = wm * 32 + mf * 16 + (lane >> 2);
                const int kc = kb + (lane & 3);
                a[mf][0] = f2tf(As[s][r0][kc]);
                a[mf][1] = f2tf(As[s][r0 + 8][kc]);
                a[mf][2] = f2tf(As[s][r0][kc + 4]);
                a[mf][3] = f2tf(As[s][r0 + 8][kc + 4]);
            }
#pragma unroll
            for (int nf = 0; nf < 4; ++nf) {
                const int c0 = wn * 32 + nf * 8 + (lane >> 2);
                const int kr = kb + (lane & 3);
                b[nf][0] = f2tf(Bs[s][kr][c0]);
                b[nf][1] = f2tf(Bs[s][kr + 4][c0]);
            }
#pragma unroll
            for (int mf = 0; mf < 2; ++mf)
#pragma unroll
                for (int nf = 0; nf < 4; ++nf)
                    mma8(acc[mf][nf], a[mf], b[nf]);
        }
        __syncthreads();
    }

#pragma unroll
    for (int mf = 0; mf < 2; ++mf) {
#pragma unroll
        for (int nf = 0; nf < 4; ++nf) {
            const int row = m0 + wm * 32 + mf * 16 + (lane >> 2);
            const int col = n0 + wn * 32 + nf * 8 + ((lane & 3) << 1);
            const float b0 = bout[col], b1 = bout[col + 1];
#pragma unroll
            for (int rr = 0; rr < 2; ++rr) {
                const float v0 = acc[mf][nf][rr * 2 + 0] + b0;
                const float v1 = acc[mf][nf][rr * 2 + 1] + b1;
                float2* p = reinterpret_cast<float2*>(
                    &out[(size_t)(row + rr * 8) * DMODEL + col]);
                *p = make_float2(v0, v1);
            }
        }
    }
#undef LOAD_STAGE2
}

// ---------------------------------------------------------------------------
// Inputs (metadata order): x, W_proj, b_proj, W_out, b_out, layer_idx, num_layers
// ---------------------------------------------------------------------------
extern "C" void kernel_launch(void* const* d_in, const int* in_sizes, int n_in,
                              void* d_out, int out_size)
{
    const float* x    = (const float*)d_in[0];
    const float* Wp   = (const float*)d_in[1];
    const float* bp   = (const float*)d_in[2];
    const float* Wout = (const float*)d_in[3];
    const float* bout = (const float*)d_in[4];
    float* out = (float*)d_out;

    const int M = in_sizes[0] / DMODEL;  // 16384

    dim3 blk(256);
    dim3 grid(DMODEL / 64, M / 128);  // x-fast over N -> consecutive CTAs share A strip in L2

    hgrn2_gate_gemm<<<grid, blk>>>(x, Wp, bp);
    hgrn2_out_gemm<<<grid, blk>>>(Wout, bout, out);
}

// round 4
// speedup vs baseline: 1.3963x; 1.3963x over previous
#include <cuda_runtime.h>
#include <cstdint>

#define DM   1024
#define DM8  128       // DM/8
#define MTOT 16384

// ---------------------------------------------------------------------------
// Static scratch: fragment-major, tf32-pre-rounded operands
//   A-frag layout: [M/16][K/8][lane 32][reg 4]   (reg: a0,a1,a2,a3 of m16n8k8)
//   B-frag layout: [N/8][K/8][lane 32][reg 2]    (reg: b0,b1)
// ---------------------------------------------------------------------------
__device__ float g_xr[(size_t)MTOT * DM];   // x, A-frag (64 MB)
__device__ float g_h [(size_t)MTOT * DM];   // h, A-frag (64 MB)
__device__ float g_Wg[(size_t)DM * DM];     // W_proj[:,0:1024], B-frag (4 MB)
__device__ float g_Wo[(size_t)DM * DM];     // W_proj[:,2048:3072], B-frag (4 MB)
__device__ float g_Wu[(size_t)DM * DM];     // W_out, B-frag (4 MB)

// ---------------------------------------------------------------------------
// helpers
// ---------------------------------------------------------------------------
__device__ __forceinline__ uint32_t smem_u32(const void* p) {
    return (uint32_t)__cvta_generic_to_shared(p);
}
__device__ __forceinline__ void cp16(uint32_t dst, const void* src) {
    asm volatile("cp.async.cg.shared.global [%0], [%1], 16;\n" ::"r"(dst), "l"(src));
}
__device__ __forceinline__ void cp_commit() { asm volatile("cp.async.commit_group;\n"); }
template <int N> __device__ __forceinline__ void cp_wait() {
    asm volatile("cp.async.wait_group %0;\n" ::"n"(N));
}
__device__ __forceinline__ uint32_t f2tf(float x) {
    uint32_t r; asm("cvt.rna.tf32.f32 %0, %1;" : "=r"(r) : "f"(x)); return r;
}
__device__ __forceinline__ void mma8(float* c, const uint32_t* a, const uint32_t* b) {
    asm volatile(
        "mma.sync.aligned.m16n8k8.row.col.f32.tf32.tf32.f32 "
        "{%0,%1,%2,%3}, {%4,%5,%6,%7}, {%8,%9}, {%0,%1,%2,%3};\n"
        : "+f"(c[0]), "+f"(c[1]), "+f"(c[2]), "+f"(c[3])
        : "r"(a[0]), "r"(a[1]), "r"(a[2]), "r"(a[3]), "r"(b[0]), "r"(b[1]));
}

// ---------------------------------------------------------------------------
// Pre-pass: x -> A-frag layout, rounded.  Tile 32 rows x 32 cols, block (32,8).
// ---------------------------------------------------------------------------
__global__ __launch_bounds__(256) void frag_x(const float* __restrict__ x) {
    __shared__ float T[32][33];
    const int tx = threadIdx.x, ty = threadIdx.y;
    const int c0 = blockIdx.x * 32, r0 = blockIdx.y * 32;
#pragma unroll
    for (int i = 0; i < 32; i += 8)
        T[ty + i][tx] = x[(size_t)(r0 + ty + i) * DM + c0 + tx];
    __syncthreads();
    const int tid = ty * 32 + tx;
    const int tl = tid >> 5, l = tid & 31;
    const int mtl = tl >> 2, ktl = tl & 3;
    const int br = mtl * 16 + (l >> 2), bc = ktl * 8 + (l & 3);
    float4 v;
    v.x = __uint_as_float(f2tf(T[br][bc]));
    v.y = __uint_as_float(f2tf(T[br + 8][bc]));
    v.z = __uint_as_float(f2tf(T[br][bc + 4]));
    v.w = __uint_as_float(f2tf(T[br + 8][bc + 4]));
    const size_t off =
        ((size_t)(blockIdx.y * 2 + mtl) * DM8 + blockIdx.x * 4 + ktl) * 128 + l * 4;
    *reinterpret_cast<float4*>(g_xr + off) = v;
}

// ---------------------------------------------------------------------------
// Pre-pass: weight slab [k][colOff+n] -> B-frag layout, rounded.
// ---------------------------------------------------------------------------
__global__ __launch_bounds__(256) void frag_w(const float* __restrict__ src,
                                              int srcCols, int colOff, int which) {
    float* dst = (which == 0) ? g_Wg : (which == 1) ? g_Wo : g_Wu;
    __shared__ float T[32][33];
    const int tx = threadIdx.x, ty = threadIdx.y;
    const int n0 = blockIdx.x * 32, k0 = blockIdx.y * 32;
#pragma unroll
    for (int i = 0; i < 32; i += 8)
        T[ty + i][tx] = src[(size_t)(k0 + ty + i) * srcCols + colOff + n0 + tx];
    __syncthreads();
    const int tid = ty * 32 + tx;
#pragma unroll
    for (int itr = 0; itr < 2; ++itr) {
        const int id = itr * 256 + tid;
        const int tl = id >> 5, l = id & 31;
        const int nbl = tl >> 2, kbl = tl & 3;
        float2 v;
        v.x = __uint_as_float(f2tf(T[kbl * 8 + (l & 3)][nbl * 8 + (l >> 2)]));
        v.y = __uint_as_float(f2tf(T[kbl * 8 + 4 + (l & 3)][nbl * 8 + (l >> 2)]));
        const size_t off =
            ((size_t)(blockIdx.x * 4 + nbl) * DM8 + blockIdx.y * 4 + kbl) * 64 + l * 2;
        *reinterpret_cast<float2*>(dst + off) = v;
    }
}

// ---------------------------------------------------------------------------
// Smem maps (dynamic, bytes). Stages and epilogue staging overlap (disjoint in
// time, separated by the loop-trailing __syncthreads).
//   gate: A[2]@0 (8KB ea), Bg[2]@16384 (4KB), Bo[2]@24576 (4KB), bias@36864
//   out : A[2]@0 (8KB),    B[2]@16384 (8KB),                      bias@36864
//   epilogue hbuf: per-warp 32x36 floats @ w*4608, region [0, 36864)
// ---------------------------------------------------------------------------
#define SMEM_BYTES 37376

// ---------------------------------------------------------------------------
// Kernel 1: G = x@Wg, O = x@Wo, h = (G+bg)*sigmoid(O+bo) -> g_h (A-frag, rounded)
// BM=128 BN=64 BK=16. 8 warps = 4(M) x 2(N), warp tile 32x32, dual accumulators.
// ---------------------------------------------------------------------------
__global__ __launch_bounds__(256, 2) void gate_gemm(const float* __restrict__ bp) {
    extern __shared__ __align__(16) char smem[];
    const uint32_t sb = smem_u32(smem);
    const int t = threadIdx.x, lane = t & 31, w = t >> 5;
    const int wm = w & 3, wn = w >> 2;
    const int n0 = blockIdx.x * 64, m0 = blockIdx.y * 128;

    float* bias = reinterpret_cast<float*>(smem + 36864);
    if (t < 64) { bias[t] = bp[n0 + t]; bias[64 + t] = bp[2048 + n0 + t]; }

    float accG[2][4][4] = {};
    float accO[2][4][4] = {};

    const int ct = t >> 5;  // chunk 0..7 (A: mt, B: nb)

    auto load_stage = [&](int kt) {
        const int s = kt & 1;
        const float* as = g_xr + ((size_t)(m0 / 16 + ct) * DM8 + kt * 2) * 128;
        const uint32_t ab = sb + s * 8192 + ct * 1024;
        cp16(ab + lane * 16, as + lane * 4);
        cp16(ab + 512 + lane * 16, as + 128 + lane * 4);
        const float* gs = g_Wg + ((size_t)(n0 / 8 + ct) * DM8 + kt * 2) * 64;
        cp16(sb + 16384 + s * 4096 + ct * 512 + lane * 16, gs + lane * 4);
        const float* os = g_Wo + ((size_t)(n0 / 8 + ct) * DM8 + kt * 2) * 64;
        cp16(sb + 24576 + s * 4096 + ct * 512 + lane * 16, os + lane * 4);
        cp_commit();
    };

    load_stage(0);
    for (int it = 0; it < 64; ++it) {
        if (it + 1 < 64) { load_stage(it + 1); cp_wait<1>(); }
        else             { cp_wait<0>(); }
        __syncthreads();
        const int s = it & 1;
        const char* A  = smem + s * 8192;
        const char* BG = smem + 16384 + s * 4096;
        const char* BO = smem + 24576 + s * 4096;
#pragma unroll
        for (int kt = 0; kt < 2; ++kt) {
            float4 av[2]; float2 gv[4], ov[4];
#pragma unroll
            for (int mf = 0; mf < 2; ++mf)
                av[mf] = *reinterpret_cast<const float4*>(
                    A + ((wm * 2 + mf) * 2 + kt) * 512 + lane * 16);
#pragma unroll
            for (int nf = 0; nf < 4; ++nf) {
                gv[nf] = *reinterpret_cast<const float2*>(
                    BG + (wn * 4 + nf) * 512 + kt * 256 + lane * 8);
                ov[nf] = *reinterpret_cast<const float2*>(
                    BO + (wn * 4 + nf) * 512 + kt * 256 + lane * 8);
            }
#pragma unroll
            for (int mf = 0; mf < 2; ++mf)
#pragma unroll
                for (int nf = 0; nf < 4; ++nf) {
                    mma8(accG[mf][nf], (const uint32_t*)&av[mf], (const uint32_t*)&gv[nf]);
                    mma8(accO[mf][nf], (const uint32_t*)&av[mf], (const uint32_t*)&ov[nf]);
                }
        }
        __syncthreads();
    }

    // Epilogue: h = (G+bg)*sigmoid(O+bo), rounded, written in A-frag layout.
    float* hb = reinterpret_cast<float*>(smem) + w * 1152;  // 32 x 36
#pragma unroll
    for (int mf = 0; mf < 2; ++mf)
#pragma unroll
        for (int nf = 0; nf < 4; ++nf)
#pragma unroll
            for (int rr = 0; rr < 2; ++rr)
#pragma unroll
                for (int j = 0; j < 2; ++j) {
                    const int row = mf * 16 + rr * 8 + (lane >> 2);
                    const int col = nf * 8 + 2 * (lane & 3) + j;
                    const float g = accG[mf][nf][rr * 2 + j] + bias[wn * 32 + col];
                    const float o = accO[mf][nf][rr * 2 + j] + bias[64 + wn * 32 + col];
                    hb[row * 36 + col] =
                        __uint_as_float(f2tf(g * (1.0f / (1.0f + __expf(-o)))));
                }
    __syncwarp();
#pragma unroll
    for (int tl = 0; tl < 8; ++tl) {
        const int mtl = tl >> 2, ktl = tl & 3;
        const int br = mtl * 16 + (lane >> 2), bc = ktl * 8 + (lane & 3);
        float4 v;
        v.x = hb[br * 36 + bc];
        v.y = hb[(br + 8) * 36 + bc];
        v.z = hb[br * 36 + bc + 4];
        v.w = hb[(br + 8) * 36 + bc + 4];
        const size_t off =
            ((size_t)(m0 / 16 + wm * 2 + mtl) * DM8 + n0 / 8 + wn * 4 + ktl) * 128 +
            lane * 4;
        *reinterpret_cast<float4*>(g_h + off) = v;
    }
}

// ---------------------------------------------------------------------------
// Kernel 2: out = h @ W_out + b_out.  BM=128 BN=128 BK=16.
// 8 warps = 2(M) x 4(N), warp tile 64x32.
// ---------------------------------------------------------------------------
__global__ __launch_bounds__(256, 2) void out_gemm(const float* __restrict__ bout,
                                                   float* __restrict__ out) {
    extern __shared__ __align__(16) char smem[];
    const uint32_t sb = smem_u32(smem);
    const int t = threadIdx.x, lane = t & 31, w = t >> 5;
    const int wm = w & 1, wn = w >> 1;
    const int n0 = blockIdx.x * 128, m0 = blockIdx.y * 128;

    float* bias = reinterpret_cast<float*>(smem + 36864);
    if (t < 128) bias[t] = bout[n0 + t];

    float acc[4][4][4] = {};

    const int mt8 = t >> 5;
    const int nb16 = t >> 4, s16 = t & 15;

    auto load_stage = [&](int kt) {
        const int s = kt & 1;
        const float* as = g_h + ((size_t)(m0 / 16 + mt8) * DM8 + kt * 2) * 128;
        const uint32_t ab = sb + s * 8192 + mt8 * 1024;
        cp16(ab + lane * 16, as + lane * 4);
        cp16(ab + 512 + lane * 16, as + 128 + lane * 4);
        const float* bs = g_Wu + ((size_t)(n0 / 8 + nb16) * DM8 + kt * 2) * 64;
        const uint32_t bb = sb + 16384 + s * 8192 + nb16 * 512 + s16 * 32;
        cp16(bb, bs + s16 * 8);
        cp16(bb + 16, bs + s16 * 8 + 4);
        cp_commit();
    };

    load_stage(0);
    for (int it = 0; it < 64; ++it) {
        if (it + 1 < 64) { load_stage(it + 1); cp_wait<1>(); }
        else             { cp_wait<0>(); }
        __syncthreads();
        const int s = it & 1;
        const char* A = smem + s * 8192;
        const char* B = smem + 16384 + s * 8192;
#pragma unroll
        for (int kt = 0; kt < 2; ++kt) {
            float4 av[4]; float2 bv[4];
#pragma unroll
            for (int mf = 0; mf < 4; ++mf)
                av[mf] = *reinterpret_cast<const float4*>(
                    A + ((wm * 4 + mf) * 2 + kt) * 512 + lane * 16);
#pragma unroll
            for (int nf = 0; nf < 4; ++nf)
                bv[nf] = *reinterpret_cast<const float2*>(
                    B + (wn * 4 + nf) * 512 + kt * 256 + lane * 8);
#pragma unroll
            for (int mf = 0; mf < 4; ++mf)
#pragma unroll
                for (int nf = 0; nf < 4; ++nf)
                    mma8(acc[mf][nf], (const uint32_t*)&av[mf], (const uint32_t*)&bv[nf]);
        }
        __syncthreads();
    }

    // Epilogue: +bias, store row-major coalesced through smem (2 chunks of 32 rows)
    float* hb = reinterpret_cast<float*>(smem) + w * 1152;  // 32 x 36
#pragma unroll
    for (int ch = 0; ch < 2; ++ch) {
#pragma unroll
        for (int mfl = 0; mfl < 2; ++mfl)
#pragma unroll
            for (int nf = 0; nf < 4; ++nf)
#pragma unroll
                for (int rr = 0; rr < 2; ++rr)
#pragma unroll
                    for (int j = 0; j < 2; ++j) {
                        const int row = mfl * 16 + rr * 8 + (lane >> 2);
                        const int col = nf * 8 + 2 * (lane & 3) + j;
                        hb[row * 36 + col] = acc[ch * 2 + mfl][nf][rr * 2 + j] +
                                             bias[wn * 32 + col];
                    }
        __syncwarp();
#pragma unroll
        for (int i = 0; i < 8; ++i) {
            const int r = i * 4 + (lane >> 3), c4 = lane & 7;
            const float4 v = *reinterpret_cast<const float4*>(hb + r * 36 + c4 * 4);
            *reinterpret_cast<float4*>(
                &out[(size_t)(m0 + wm * 64 + ch * 32 + r) * DM + n0 + wn * 32 + c4 * 4]) = v;
        }
        __syncwarp();
    }
}

// ---------------------------------------------------------------------------
// Inputs (metadata order): x, W_proj, b_proj, W_out, b_out, layer_idx, num_layers
// ---------------------------------------------------------------------------
extern "C" void kernel_launch(void* const* d_in, const int* in_sizes, int n_in,
                              void* d_out, int out_size)
{
    const float* x    = (const float*)d_in[0];
    const float* Wp   = (const float*)d_in[1];
    const float* bp   = (const float*)d_in[2];
    const float* Wout = (const float*)d_in[3];
    const float* bout = (const float*)d_in[4];
    float* out = (float*)d_out;

    cudaFuncSetAttribute(gate_gemm, cudaFuncAttributeMaxDynamicSharedMemorySize,
                         SMEM_BYTES);
    cudaFuncSetAttribute(out_gemm, cudaFuncAttributeMaxDynamicSharedMemorySize,
                         SMEM_BYTES);

    dim3 tpb(32, 8);
    frag_x<<<dim3(DM / 32, MTOT / 32), tpb>>>(x);
    frag_w<<<dim3(32, 32), tpb>>>(Wp,   3072, 0,    0);  // -> g_Wg
    frag_w<<<dim3(32, 32), tpb>>>(Wp,   3072, 2048, 1);  // -> g_Wo
    frag_w<<<dim3(32, 32), tpb>>>(Wout, 1024, 0,    2);  // -> g_Wu

    gate_gemm<<<dim3(16, 128), 256, SMEM_BYTES>>>(bp);
    out_gemm <<<dim3(8, 128),  256, SMEM_BYTES>>>(bout, out);
}

// round 5
// speedup vs baseline: 1.5298x; 1.0956x over previous
#include <cuda_runtime.h>
#include <cstdint>

#define DM   1024
#define DM8  128       // DM/8
#define MTOT 16384

// ---------------------------------------------------------------------------
// Static scratch: fragment-major, tf32-pre-rounded operands
//   A-frag: [M/16][K/8][lane 32][reg 4]           (m16n8k8 a0..a3)
//   g_Wgo : [N/8][K/8][lane 32][g_b0,g_b1,o_b0,o_b1]  (gate weights interleaved)
//   g_Wup : [N/8][K/16][lane 32][b0_e,b1_e,b0_o,b1_o] (W_out, kb pairs packed)
// ---------------------------------------------------------------------------
__device__ float g_xr [(size_t)MTOT * DM];        // 64 MB
__device__ float g_h  [(size_t)MTOT * DM];        // 64 MB
__device__ float g_Wgo[(size_t)2 * DM * DM];      // 8 MB
__device__ float g_Wup[(size_t)DM * DM];          // 4 MB

// ---------------------------------------------------------------------------
// helpers
// ---------------------------------------------------------------------------
__device__ __forceinline__ uint32_t smem_u32(const void* p) {
    return (uint32_t)__cvta_generic_to_shared(p);
}
__device__ __forceinline__ void cp16(uint32_t dst, const void* src) {
    asm volatile("cp.async.cg.shared.global [%0], [%1], 16;\n" ::"r"(dst), "l"(src));
}
__device__ __forceinline__ void cp_commit() { asm volatile("cp.async.commit_group;\n"); }
template <int N> __device__ __forceinline__ void cp_wait() {
    asm volatile("cp.async.wait_group %0;\n" ::"n"(N));
}
__device__ __forceinline__ uint32_t f2tf(float x) {
    uint32_t r; asm("cvt.rna.tf32.f32 %0, %1;" : "=r"(r) : "f"(x)); return r;
}
__device__ __forceinline__ void mma8(float* c, const uint32_t* a, const uint32_t* b) {
    asm volatile(
        "mma.sync.aligned.m16n8k8.row.col.f32.tf32.tf32.f32 "
        "{%0,%1,%2,%3}, {%4,%5,%6,%7}, {%8,%9}, {%0,%1,%2,%3};\n"
        : "+f"(c[0]), "+f"(c[1]), "+f"(c[2]), "+f"(c[3])
        : "r"(a[0]), "r"(a[1]), "r"(a[2]), "r"(a[3]), "r"(b[0]), "r"(b[1]));
}

// ---------------------------------------------------------------------------
// Pre-pass: x -> A-frag layout, rounded
// ---------------------------------------------------------------------------
__global__ __launch_bounds__(256) void frag_x(const float* __restrict__ x) {
    __shared__ float T[32][33];
    const int tx = threadIdx.x, ty = threadIdx.y;
    const int c0 = blockIdx.x * 32, r0 = blockIdx.y * 32;
#pragma unroll
    for (int i = 0; i < 32; i += 8)
        T[ty + i][tx] = x[(size_t)(r0 + ty + i) * DM + c0 + tx];
    __syncthreads();
    const int tid = ty * 32 + tx;
    const int tl = tid >> 5, l = tid & 31;
    const int mtl = tl >> 2, ktl = tl & 3;
    const int br = mtl * 16 + (l >> 2), bc = ktl * 8 + (l & 3);
    float4 v;
    v.x = __uint_as_float(f2tf(T[br][bc]));
    v.y = __uint_as_float(f2tf(T[br + 8][bc]));
    v.z = __uint_as_float(f2tf(T[br][bc + 4]));
    v.w = __uint_as_float(f2tf(T[br + 8][bc + 4]));
    const size_t off =
        ((size_t)(blockIdx.y * 2 + mtl) * DM8 + blockIdx.x * 4 + ktl) * 128 + l * 4;
    *reinterpret_cast<float4*>(g_xr + off) = v;
}

// ---------------------------------------------------------------------------
// Pre-pass: weight slab -> interleaved/packed B-frag layouts
//   which 0: Wg -> g_Wgo slots [0,1]   which 1: Wo -> g_Wgo slots [2,3]
//   which 2: W_out -> g_Wup, kb pair packing
// ---------------------------------------------------------------------------
__global__ __launch_bounds__(256) void frag_w(const float* __restrict__ src,
                                              int srcCols, int colOff, int which) {
    __shared__ float T[32][33];
    const int tx = threadIdx.x, ty = threadIdx.y;
    const int n0 = blockIdx.x * 32, k0 = blockIdx.y * 32;
#pragma unroll
    for (int i = 0; i < 32; i += 8)
        T[ty + i][tx] = src[(size_t)(k0 + ty + i) * srcCols + colOff + n0 + tx];
    __syncthreads();
    const int tid = ty * 32 + tx;
#pragma unroll
    for (int itr = 0; itr < 2; ++itr) {
        const int id = itr * 256 + tid;
        const int tl = id >> 5, l = id & 31;
        const int nbl = tl >> 2, kbl = tl & 3;
        const int nbg = blockIdx.x * 4 + nbl, kbg = blockIdx.y * 4 + kbl;
        float2 v;
        v.x = __uint_as_float(f2tf(T[kbl * 8 + (l & 3)][nbl * 8 + (l >> 2)]));
        v.y = __uint_as_float(f2tf(T[kbl * 8 + 4 + (l & 3)][nbl * 8 + (l >> 2)]));
        if (which < 2) {
            const size_t off = (((size_t)nbg * DM8 + kbg) * 32 + l) * 4 + which * 2;
            *reinterpret_cast<float2*>(g_Wgo + off) = v;
        } else {
            const size_t off =
                (((size_t)nbg * 64 + (kbg >> 1)) * 32 + l) * 4 + (kbg & 1) * 2;
            *reinterpret_cast<float2*>(g_Wup + off) = v;
        }
    }
}

// ---------------------------------------------------------------------------
// Smem: 3 stages x 32KB (A 16KB @ +0, B 16KB @ +16384), bias @ 98304.
// Epilogue hbuf reuses [0, 36864) after a sync.
// ---------------------------------------------------------------------------
#define STAGE_B 32768
#define SMEM_BYTES (3 * STAGE_B + 1024)   // 99328

// ---------------------------------------------------------------------------
// Kernel 1: G = x@Wg, O = x@Wo, h = (G+bg)*sigmoid(O+bo) -> g_h (A-frag)
// BM=128 BN=64 BK=32. 8 warps = 4(M) x 2(N), warp tile 32x32, dual acc.
// ---------------------------------------------------------------------------
__global__ __launch_bounds__(256, 2) void gate_gemm(const float* __restrict__ bp) {
    extern __shared__ __align__(16) char smem[];
    const uint32_t sb = smem_u32(smem);
    const int t = threadIdx.x, lane = t & 31, w = t >> 5;
    const int wm = w & 3, wn = w >> 2;
    const int n0 = blockIdx.x * 64, m0 = blockIdx.y * 128;

    float* bias = reinterpret_cast<float*>(smem + 3 * STAGE_B);
    if (t < 64) { bias[t] = bp[n0 + t]; bias[64 + t] = bp[2048 + n0 + t]; }

    float accG[2][4][4] = {};
    float accO[2][4][4] = {};

    auto load_stage = [&](int kt) {
        const int s = kt % 3;
        const float* as = g_xr + ((size_t)(m0 / 16 + w) * DM8 + kt * 4) * 128;
        const float* bs = g_Wgo + ((size_t)(n0 / 8 + w) * DM8 + kt * 4) * 128;
        const uint32_t ab = sb + s * STAGE_B + w * 2048;
        const uint32_t bb = sb + s * STAGE_B + 16384 + w * 2048;
#pragma unroll
        for (int k = 0; k < 4; ++k) {
            cp16(ab + k * 512 + lane * 16, as + k * 128 + lane * 4);
            cp16(bb + k * 512 + lane * 16, bs + k * 128 + lane * 4);
        }
        cp_commit();
    };

    load_stage(0);
    load_stage(1);

    for (int it = 0; it < 32; ++it) {
        if (it + 1 < 32) cp_wait<1>(); else cp_wait<0>();
        __syncthreads();
        if (it + 2 < 32) load_stage(it + 2);
        const int s = it % 3;
        const char* A = smem + s * STAGE_B;
        const char* B = smem + s * STAGE_B + 16384;
#pragma unroll
        for (int kt = 0; kt < 4; ++kt) {
            float4 av[2], bv[4];
#pragma unroll
            for (int mf = 0; mf < 2; ++mf)
                av[mf] = *reinterpret_cast<const float4*>(
                    A + (((wm * 2 + mf) * 4 + kt) * 32 + lane) * 16);
#pragma unroll
            for (int nf = 0; nf < 4; ++nf)
                bv[nf] = *reinterpret_cast<const float4*>(
                    B + (((wn * 4 + nf) * 4 + kt) * 32 + lane) * 16);
#pragma unroll
            for (int mf = 0; mf < 2; ++mf)
#pragma unroll
                for (int nf = 0; nf < 4; ++nf) {
                    mma8(accG[mf][nf], (const uint32_t*)&av[mf],
                         (const uint32_t*)&bv[nf].x);
                    mma8(accO[mf][nf], (const uint32_t*)&av[mf],
                         (const uint32_t*)&bv[nf].z);
                }
        }
    }

    __syncthreads();  // hbuf region overlaps stage smem

    // Epilogue: h = (G+bg)*sigmoid(O+bo), rounded, A-frag layout into g_h
    float* hb = reinterpret_cast<float*>(smem) + w * 1152;  // 32 x 36
#pragma unroll
    for (int mf = 0; mf < 2; ++mf)
#pragma unroll
        for (int nf = 0; nf < 4; ++nf)
#pragma unroll
            for (int rr = 0; rr < 2; ++rr)
#pragma unroll
                for (int j = 0; j < 2; ++j) {
                    const int row = mf * 16 + rr * 8 + (lane >> 2);
                    const int col = nf * 8 + 2 * (lane & 3) + j;
                    const float g = accG[mf][nf][rr * 2 + j] + bias[wn * 32 + col];
                    const float o = accO[mf][nf][rr * 2 + j] + bias[64 + wn * 32 + col];
                    hb[row * 36 + col] =
                        __uint_as_float(f2tf(g * (1.0f / (1.0f + __expf(-o)))));
                }
    __syncwarp();
#pragma unroll
    for (int tl = 0; tl < 8; ++tl) {
        const int mtl = tl >> 2, ktl = tl & 3;
        const int br = mtl * 16 + (lane >> 2), bc = ktl * 8 + (lane & 3);
        float4 v;
        v.x = hb[br * 36 + bc];
        v.y = hb[(br + 8) * 36 + bc];
        v.z = hb[br * 36 + bc + 4];
        v.w = hb[(br + 8) * 36 + bc + 4];
        const size_t off =
            ((size_t)(m0 / 16 + wm * 2 + mtl) * DM8 + n0 / 8 + wn * 4 + ktl) * 128 +
            lane * 4;
        *reinterpret_cast<float4*>(g_h + off) = v;
    }
}

// ---------------------------------------------------------------------------
// Kernel 2: out = h @ W_out + b_out.  BM=128 BN=128 BK=32.
// 8 warps = 2(M) x 4(N), warp tile 64x32.
// ---------------------------------------------------------------------------
__global__ __launch_bounds__(256, 2) void out_gemm(const float* __restrict__ bout,
                                                   float* __restrict__ out) {
    extern __shared__ __align__(16) char smem[];
    const uint32_t sb = smem_u32(smem);
    const int t = threadIdx.x, lane = t & 31, w = t >> 5;
    const int wm = w & 1, wn = w >> 1;
    const int n0 = blockIdx.x * 128, m0 = blockIdx.y * 128;

    float* bias = reinterpret_cast<float*>(smem + 3 * STAGE_B);
    if (t < 128) bias[t] = bout[n0 + t];

    float acc[4][4][4] = {};

    auto load_stage = [&](int kt) {
        const int s = kt % 3;
        const float* as = g_h + ((size_t)(m0 / 16 + w) * DM8 + kt * 4) * 128;
        const uint32_t ab = sb + s * STAGE_B + w * 2048;
#pragma unroll
        for (int k = 0; k < 4; ++k)
            cp16(ab + k * 512 + lane * 16, as + k * 128 + lane * 4);
#pragma unroll
        for (int i = 0; i < 4; ++i) {
            const int lin = i * 256 + t;
            const int nb = lin >> 6, rem = lin & 63;
            const int ktp = rem >> 5, l2 = rem & 31;
            cp16(sb + s * STAGE_B + 16384 + lin * 16,
                 g_Wup + ((size_t)(n0 / 8 + nb) * 64 + kt * 2 + ktp) * 128 + l2 * 4);
        }
        cp_commit();
    };

    load_stage(0);
    load_stage(1);

    for (int it = 0; it < 32; ++it) {
        if (it + 1 < 32) cp_wait<1>(); else cp_wait<0>();
        __syncthreads();
        if (it + 2 < 32) load_stage(it + 2);
        const int s = it % 3;
        const char* A = smem + s * STAGE_B;
        const char* B = smem + s * STAGE_B + 16384;
#pragma unroll
        for (int ktp = 0; ktp < 2; ++ktp) {
            float4 bv[4];
#pragma unroll
            for (int nf = 0; nf < 4; ++nf)
                bv[nf] = *reinterpret_cast<const float4*>(
                    B + (((wn * 4 + nf) * 2 + ktp) * 32 + lane) * 16);
#pragma unroll
            for (int kts = 0; kts < 2; ++kts) {
                const int kt = ktp * 2 + kts;
                float4 av[4];
#pragma unroll
                for (int mf = 0; mf < 4; ++mf)
                    av[mf] = *reinterpret_cast<const float4*>(
                        A + (((wm * 4 + mf) * 4 + kt) * 32 + lane) * 16);
#pragma unroll
                for (int mf = 0; mf < 4; ++mf)
#pragma unroll
                    for (int nf = 0; nf < 4; ++nf)
                        mma8(acc[mf][nf], (const uint32_t*)&av[mf],
                             kts ? (const uint32_t*)&bv[nf].z
                                 : (const uint32_t*)&bv[nf].x);
            }
        }
    }

    __syncthreads();  // hbuf region overlaps stage smem

    // Epilogue: +bias, coalesced row-major store via smem
    float* hb = reinterpret_cast<float*>(smem) + w * 1152;  // 32 x 36
#pragma unroll
    for (int ch = 0; ch < 2; ++ch) {
#pragma unroll
        for (int mfl = 0; mfl < 2; ++mfl)
#pragma unroll
            for (int nf = 0; nf < 4; ++nf)
#pragma unroll
                for (int rr = 0; rr < 2; ++rr)
#pragma unroll
                    for (int j = 0; j < 2; ++j) {
                        const int row = mfl * 16 + rr * 8 + (lane >> 2);
                        const int col = nf * 8 + 2 * (lane & 3) + j;
                        hb[row * 36 + col] = acc[ch * 2 + mfl][nf][rr * 2 + j] +
                                             bias[wn * 32 + col];
                    }
        __syncwarp();
#pragma unroll
        for (int i = 0; i < 8; ++i) {
            const int r = i * 4 + (lane >> 3), c4 = lane & 7;
            const float4 v = *reinterpret_cast<const float4*>(hb + r * 36 + c4 * 4);
            *reinterpret_cast<float4*>(
                &out[(size_t)(m0 + wm * 64 + ch * 32 + r) * DM + n0 + wn * 32 +
                     c4 * 4]) = v;
        }
        __syncwarp();
    }
}

// ---------------------------------------------------------------------------
// Inputs (metadata order): x, W_proj, b_proj, W_out, b_out, layer_idx, num_layers
// ---------------------------------------------------------------------------
extern "C" void kernel_launch(void* const* d_in, const int* in_sizes, int n_in,
                              void* d_out, int out_size)
{
    const float* x    = (const float*)d_in[0];
    const float* Wp   = (const float*)d_in[1];
    const float* bp   = (const float*)d_in[2];
    const float* Wout = (const float*)d_in[3];
    const float* bout = (const float*)d_in[4];
    float* out = (float*)d_out;

    cudaFuncSetAttribute(gate_gemm, cudaFuncAttributeMaxDynamicSharedMemorySize,
                         SMEM_BYTES);
    cudaFuncSetAttribute(out_gemm, cudaFuncAttributeMaxDynamicSharedMemorySize,
                         SMEM_BYTES);

    dim3 tpb(32, 8);
    frag_x<<<dim3(DM / 32, MTOT / 32), tpb>>>(x);
    frag_w<<<dim3(32, 32), tpb>>>(Wp,   3072, 0,    0);  // Wg -> g_Wgo[.,0:2]
    frag_w<<<dim3(32, 32), tpb>>>(Wp,   3072, 2048, 1);  // Wo -> g_Wgo[.,2:4]
    frag_w<<<dim3(32, 32), tpb>>>(Wout, 1024, 0,    2);  // -> g_Wup

    gate_gemm<<<dim3(16, 128), 256, SMEM_BYTES>>>(bp);
    out_gemm <<<dim3(8, 128),  256, SMEM_BYTES>>>(bout, out);
}

// round 6
// speedup vs baseline: 2.7439x; 1.7937x over previous
#include <cuda_runtime.h>
#include <cuda_fp16.h>
#include <cstdint>

#define DM    1024
#define DM16  64          // DM / 16 (k16 tiles)
#define MTOT  16384

// ---------------------------------------------------------------------------
// Static scratch, fp16 fragment-major (m16n8k16):
//   A-frag: [M/16][K/16][lane 32][4 u32]  (a0..a3, each half2)
//   g_Wgo : [N/8][K/16][lane 32][g_b0,g_b1,o_b0,o_b1]
//   g_Wup : [N/8][K/32][lane 32][b0_e,b1_e,b0_o,b1_o]  (k16 pairs packed)
// ---------------------------------------------------------------------------
__device__ uint32_t g_xr [(size_t)(MTOT / 16) * DM16 * 128];  // 32 MB
__device__ uint32_t g_h  [(size_t)(MTOT / 16) * DM16 * 128];  // 32 MB
__device__ uint32_t g_Wgo[(size_t)128 * DM16 * 128];          // 4 MB
__device__ uint32_t g_Wup[(size_t)128 * 32 * 128];            // 2 MB

// ---------------------------------------------------------------------------
// helpers
// ---------------------------------------------------------------------------
__device__ __forceinline__ uint32_t smem_u32(const void* p) {
    return (uint32_t)__cvta_generic_to_shared(p);
}
__device__ __forceinline__ void cp16(uint32_t dst, const void* src) {
    asm volatile("cp.async.cg.shared.global [%0], [%1], 16;\n" ::"r"(dst), "l"(src));
}
__device__ __forceinline__ void cp_commit() { asm volatile("cp.async.commit_group;\n"); }
template <int N> __device__ __forceinline__ void cp_wait() {
    asm volatile("cp.async.wait_group %0;\n" ::"n"(N));
}
// pack two fp32 -> half2 (lo = first element, in low 16 bits)
__device__ __forceinline__ uint32_t h2(float lo, float hi) {
    uint32_t r;
    asm("cvt.rn.f16x2.f32 %0, %1, %2;" : "=r"(r) : "f"(hi), "f"(lo));
    return r;
}
__device__ __forceinline__ void mma16(float* c, const uint32_t* a, uint32_t b0,
                                      uint32_t b1) {
    asm volatile(
        "mma.sync.aligned.m16n8k16.row.col.f32.f16.f16.f32 "
        "{%0,%1,%2,%3}, {%4,%5,%6,%7}, {%8,%9}, {%0,%1,%2,%3};\n"
        : "+f"(c[0]), "+f"(c[1]), "+f"(c[2]), "+f"(c[3])
        : "r"(a[0]), "r"(a[1]), "r"(a[2]), "r"(a[3]), "r"(b0), "r"(b1));
}

// ---------------------------------------------------------------------------
// Pre-pass: x -> fp16 A-frag layout.  Tile 32 rows x 64 cols.
// ---------------------------------------------------------------------------
__global__ __launch_bounds__(256) void frag_x(const float* __restrict__ x) {
    __shared__ float T[32][65];
    const int tid = threadIdx.x;
    const int c0 = blockIdx.x * 64, r0 = blockIdx.y * 32;
#pragma unroll
    for (int i = 0; i < 8; ++i) {
        const int lin = i * 256 + tid;
        const int r = lin >> 6, c = lin & 63;
        T[r][c] = x[(size_t)(r0 + r) * DM + c0 + c];
    }
    __syncthreads();
    const int tl = tid >> 5, l = tid & 31;
    const int mtl = tl >> 2, ktl = tl & 3;
    const int r = mtl * 16 + (l >> 2), c = ktl * 16 + (l & 3) * 2;
    uint4 v;
    v.x = h2(T[r][c],         T[r][c + 1]);
    v.y = h2(T[r + 8][c],     T[r + 8][c + 1]);
    v.z = h2(T[r][c + 8],     T[r][c + 9]);
    v.w = h2(T[r + 8][c + 8], T[r + 8][c + 9]);
    const size_t off =
        ((size_t)(blockIdx.y * 2 + mtl) * DM16 + blockIdx.x * 4 + ktl) * 128 + l * 4;
    *reinterpret_cast<uint4*>(g_xr + off) = v;
}

// ---------------------------------------------------------------------------
// Pre-pass: weight slab -> fp16 B-frag layouts.  Tile 32 n x 32 k.
//   which 0: Wg -> g_Wgo[.,0:2]   which 1: Wo -> g_Wgo[.,2:4]
//   which 2: W_out -> g_Wup (k16-pair packed)
// ---------------------------------------------------------------------------
__global__ __launch_bounds__(256) void frag_w(const float* __restrict__ src,
                                              int srcCols, int colOff, int which) {
    __shared__ float T[32][33];  // T[k][n]
    const int tid = threadIdx.x;
    const int n0 = blockIdx.x * 32, k0 = blockIdx.y * 32;
#pragma unroll
    for (int i = 0; i < 4; ++i) {
        const int lin = i * 256 + tid;
        const int k = lin >> 5, n = lin & 31;
        T[k][n] = src[(size_t)(k0 + k) * srcCols + colOff + n0 + n];
    }
    __syncthreads();
    const int tl = tid >> 5, l = tid & 31;
    const int nbl = tl >> 1, ktl = tl & 1;
    const int n = nbl * 8 + (l >> 2), kk = ktl * 16 + (l & 3) * 2;
    uint2 v;
    v.x = h2(T[kk][n],     T[kk + 1][n]);
    v.y = h2(T[kk + 8][n], T[kk + 9][n]);
    const int nbg = blockIdx.x * 4 + nbl, ktg = blockIdx.y * 2 + ktl;
    if (which < 2) {
        const size_t off = ((size_t)nbg * DM16 + ktg) * 128 + l * 4 + which * 2;
        *reinterpret_cast<uint2*>(g_Wgo + off) = v;
    } else {
        const size_t off =
            ((size_t)nbg * 32 + (ktg >> 1)) * 128 + l * 4 + (ktg & 1) * 2;
        *reinterpret_cast<uint2*>(g_Wup + off) = v;
    }
}

// ---------------------------------------------------------------------------
// Smem: 3 stages x 32KB (A 16KB, B 16KB), bias @ 98304.
// ---------------------------------------------------------------------------
#define STAGE_B 32768
#define SMEM_BYTES (3 * STAGE_B + 1024)   // 99328

// ---------------------------------------------------------------------------
// Kernel 1: G = x@Wg, O = x@Wo, h = (G+bg)*sigmoid(O+bo) -> g_h (fp16 A-frag)
// BM=128 BN=64 BK=64, 16 iters. 8 warps = 4(M) x 2(N), warp tile 32x32.
// ---------------------------------------------------------------------------
__global__ __launch_bounds__(256, 2) void gate_gemm(const float* __restrict__ bp) {
    extern __shared__ __align__(16) char smem[];
    const uint32_t sb = smem_u32(smem);
    const int t = threadIdx.x, lane = t & 31, w = t >> 5;
    const int wm = w & 3, wn = w >> 2;
    const int n0 = blockIdx.x * 64, m0 = blockIdx.y * 128;

    float* bias = reinterpret_cast<float*>(smem + 3 * STAGE_B);
    if (t < 64) { bias[t] = bp[n0 + t]; bias[64 + t] = bp[2048 + n0 + t]; }

    float accG[2][4][4] = {};
    float accO[2][4][4] = {};

    auto load_stage = [&](int it) {
        const int s = it % 3;
        const uint32_t* as = g_xr + ((size_t)(m0 / 16 + w) * DM16 + it * 4) * 128;
        const uint32_t* bs = g_Wgo + ((size_t)(n0 / 8 + w) * DM16 + it * 4) * 128;
        const uint32_t ab = sb + s * STAGE_B + w * 2048;
        const uint32_t bb = sb + s * STAGE_B + 16384 + w * 2048;
#pragma unroll
        for (int k = 0; k < 4; ++k) {
            cp16(ab + k * 512 + lane * 16, as + k * 128 + lane * 4);
            cp16(bb + k * 512 + lane * 16, bs + k * 128 + lane * 4);
        }
        cp_commit();
    };

    load_stage(0);
    load_stage(1);

    for (int it = 0; it < 16; ++it) {
        if (it + 1 < 16) cp_wait<1>(); else cp_wait<0>();
        __syncthreads();
        if (it + 2 < 16) load_stage(it + 2);
        const int s = it % 3;
        const char* A = smem + s * STAGE_B;
        const char* B = smem + s * STAGE_B + 16384;
#pragma unroll
        for (int kt = 0; kt < 4; ++kt) {
            uint4 av[2], bv[4];
#pragma unroll
            for (int mf = 0; mf < 2; ++mf)
                av[mf] = *reinterpret_cast<const uint4*>(
                    A + (((wm * 2 + mf) * 4 + kt) * 32 + lane) * 16);
#pragma unroll
            for (int nf = 0; nf < 4; ++nf)
                bv[nf] = *reinterpret_cast<const uint4*>(
                    B + (((wn * 4 + nf) * 4 + kt) * 32 + lane) * 16);
#pragma unroll
            for (int mf = 0; mf < 2; ++mf)
#pragma unroll
                for (int nf = 0; nf < 4; ++nf) {
                    mma16(accG[mf][nf], &av[mf].x, bv[nf].x, bv[nf].y);
                    mma16(accO[mf][nf], &av[mf].x, bv[nf].z, bv[nf].w);
                }
        }
    }

    __syncthreads();  // epilogue staging reuses stage smem

    // h = (G+bg)*sigmoid(O+bo) -> packed half2 -> A-frag gather -> g_h
    uint32_t* hb = reinterpret_cast<uint32_t*>(smem) + w * 640;  // 32 x 20 u32
#pragma unroll
    for (int mf = 0; mf < 2; ++mf)
#pragma unroll
        for (int nf = 0; nf < 4; ++nf)
#pragma unroll
            for (int rr = 0; rr < 2; ++rr) {
                const int row = mf * 16 + rr * 8 + (lane >> 2);
                const int col2 = nf * 4 + (lane & 3);
                const float g0 = accG[mf][nf][rr * 2]     + bias[wn * 32 + col2 * 2];
                const float g1 = accG[mf][nf][rr * 2 + 1] + bias[wn * 32 + col2 * 2 + 1];
                const float o0 = accO[mf][nf][rr * 2]     + bias[64 + wn * 32 + col2 * 2];
                const float o1 = accO[mf][nf][rr * 2 + 1] + bias[64 + wn * 32 + col2 * 2 + 1];
                const float h0 = g0 * (1.0f / (1.0f + __expf(-o0)));
                const float h1 = g1 * (1.0f / (1.0f + __expf(-o1)));
                hb[row * 20 + col2] = h2(h0, h1);
            }
    __syncwarp();
#pragma unroll
    for (int mtl = 0; mtl < 2; ++mtl)
#pragma unroll
        for (int ktl = 0; ktl < 2; ++ktl) {
            const int r = mtl * 16 + (lane >> 2), c2 = ktl * 8 + (lane & 3);
            uint4 v;
            v.x = hb[r * 20 + c2];
            v.y = hb[(r + 8) * 20 + c2];
            v.z = hb[r * 20 + c2 + 4];
            v.w = hb[(r + 8) * 20 + c2 + 4];
            const size_t off =
                ((size_t)(m0 / 16 + wm * 2 + mtl) * DM16 + n0 / 16 + wn * 2 + ktl) *
                    128 + lane * 4;
            *reinterpret_cast<uint4*>(g_h + off) = v;
        }
}

// ---------------------------------------------------------------------------
// Kernel 2: out = h @ W_out + b_out.  BM=128 BN=128 BK=64, 16 iters.
// 8 warps = 2(M) x 4(N), warp tile 64x32.
// ---------------------------------------------------------------------------
__global__ __launch_bounds__(256, 2) void out_gemm(const float* __restrict__ bout,
                                                   float* __restrict__ out) {
    extern __shared__ __align__(16) char smem[];
    const uint32_t sb = smem_u32(smem);
    const int t = threadIdx.x, lane = t & 31, w = t >> 5;
    const int wm = w & 1, wn = w >> 1;
    const int n0 = blockIdx.x * 128, m0 = blockIdx.y * 128;

    float* bias = reinterpret_cast<float*>(smem + 3 * STAGE_B);
    if (t < 128) bias[t] = bout[n0 + t];

    float acc[4][4][4] = {};

    auto load_stage = [&](int it) {
        const int s = it % 3;
        const uint32_t* as = g_h + ((size_t)(m0 / 16 + w) * DM16 + it * 4) * 128;
        const uint32_t ab = sb + s * STAGE_B + w * 2048;
#pragma unroll
        for (int k = 0; k < 4; ++k)
            cp16(ab + k * 512 + lane * 16, as + k * 128 + lane * 4);
#pragma unroll
        for (int i = 0; i < 4; ++i) {
            const int lin = i * 256 + t;
            const int nb = lin >> 6, rem = lin & 63;
            const int ktp = rem >> 5, l2 = rem & 31;
            cp16(sb + s * STAGE_B + 16384 + lin * 16,
                 g_Wup + ((size_t)(n0 / 8 + nb) * 32 + it * 2 + ktp) * 128 + l2 * 4);
        }
        cp_commit();
    };

    load_stage(0);
    load_stage(1);

    for (int it = 0; it < 16; ++it) {
        if (it + 1 < 16) cp_wait<1>(); else cp_wait<0>();
        __syncthreads();
        if (it + 2 < 16) load_stage(it + 2);
        const int s = it % 3;
        const char* A = smem + s * STAGE_B;
        const char* B = smem + s * STAGE_B + 16384;
#pragma unroll
        for (int ktp = 0; ktp < 2; ++ktp) {
            uint4 bv[4];
#pragma unroll
            for (int nf = 0; nf < 4; ++nf)
                bv[nf] = *reinterpret_cast<const uint4*>(
                    B + (((wn * 4 + nf) * 2 + ktp) * 32 + lane) * 16);
#pragma unroll
            for (int kts = 0; kts < 2; ++kts) {
                const int kt = ktp * 2 + kts;
                uint4 av[4];
#pragma unroll
                for (int mf = 0; mf < 4; ++mf)
                    av[mf] = *reinterpret_cast<const uint4*>(
                        A + (((wm * 4 + mf) * 4 + kt) * 32 + lane) * 16);
#pragma unroll
                for (int mf = 0; mf < 4; ++mf)
#pragma unroll
                    for (int nf = 0; nf < 4; ++nf)
                        mma16(acc[mf][nf], &av[mf].x,
                              kts ? bv[nf].z : bv[nf].x,
                              kts ? bv[nf].w : bv[nf].y);
            }
        }
    }

    __syncthreads();  // epilogue staging reuses stage smem

    // +bias, coalesced fp32 row-major store via smem
    float* hb = reinterpret_cast<float*>(smem) + w * 1152;  // 32 x 36 floats
#pragma unroll
    for (int ch = 0; ch < 2; ++ch) {
#pragma unroll
        for (int mfl = 0; mfl < 2; ++mfl)
#pragma unroll
            for (int nf = 0; nf < 4; ++nf)
#pragma unroll
                for (int rr = 0; rr < 2; ++rr)
#pragma unroll
                    for (int j = 0; j < 2; ++j) {
                        const int row = mfl * 16 + rr * 8 + (lane >> 2);
                        const int col = nf * 8 + 2 * (lane & 3) + j;
                        hb[row * 36 + col] = acc[ch * 2 + mfl][nf][rr * 2 + j] +
                                             bias[wn * 32 + col];
                    }
        __syncwarp();
#pragma unroll
        for (int i = 0; i < 8; ++i) {
            const int r = i * 4 + (lane >> 3), c4 = lane & 7;
            const float4 v = *reinterpret_cast<const float4*>(hb + r * 36 + c4 * 4);
            *reinterpret_cast<float4*>(
                &out[(size_t)(m0 + wm * 64 + ch * 32 + r) * DM + n0 + wn * 32 +
                     c4 * 4]) = v;
        }
        __syncwarp();
    }
}

// ---------------------------------------------------------------------------
// Inputs (metadata order): x, W_proj, b_proj, W_out, b_out, layer_idx, num_layers
// ---------------------------------------------------------------------------
extern "C" void kernel_launch(void* const* d_in, const int* in_sizes, int n_in,
                              void* d_out, int out_size)
{
    const float* x    = (const float*)d_in[0];
    const float* Wp   = (const float*)d_in[1];
    const float* bp   = (const float*)d_in[2];
    const float* Wout = (const float*)d_in[3];
    const float* bout = (const float*)d_in[4];
    float* out = (float*)d_out;

    cudaFuncSetAttribute(gate_gemm, cudaFuncAttributeMaxDynamicSharedMemorySize,
                         SMEM_BYTES);
    cudaFuncSetAttribute(out_gemm, cudaFuncAttributeMaxDynamicSharedMemorySize,
                         SMEM_BYTES);

    frag_x<<<dim3(DM / 64, MTOT / 32), 256>>>(x);
    frag_w<<<dim3(32, 32), 256>>>(Wp,   3072, 0,    0);  // Wg -> g_Wgo[.,0:2]
    frag_w<<<dim3(32, 32), 256>>>(Wp,   3072, 2048, 1);  // Wo -> g_Wgo[.,2:4]
    frag_w<<<dim3(32, 32), 256>>>(Wout, 1024, 0,    2);  // -> g_Wup

    gate_gemm<<<dim3(16, 128), 256, SMEM_BYTES>>>(bp);
    out_gemm <<<dim3(8, 128),  256, SMEM_BYTES>>>(bout, out);
}